// round 7
// baseline (speedup 1.0000x reference)
#include <cuda_runtime.h>
#include <cuda_bf16.h>
#include <mma.h>
#include <cstdint>

using namespace nvcuda;

// Shapes (fixed by problem)
#define BB 32
#define KK 512
#define TT 8
#define DD 256
#define CC 64
#define HH 128
#define WW 128

// ---------------- scratch (static device globals; no cudaMalloc) ----------------
__device__ __align__(16) __nv_bfloat16 g_value[(size_t)BB * HH * WW * DD]; // 256MB NHWC bf16
__device__ __align__(16) float g_ctx[(size_t)BB * KK * DD];                // 16MB
__device__ __align__(16) __nv_bfloat16 g_wT[9 * CC * DD];                  // [tap][ic][oc] bf16

// ---------------- cp.async helpers ----------------
__device__ __forceinline__ void cp_async16(void* smem_dst, const void* gsrc) {
    unsigned int s = (unsigned int)__cvta_generic_to_shared(smem_dst);
    asm volatile("cp.async.cg.shared.global [%0], [%1], 16;\n" ::"r"(s), "l"(gsrc));
}
__device__ __forceinline__ void cp_commit() { asm volatile("cp.async.commit_group;\n"); }
__device__ __forceinline__ void cp_wait2() { asm volatile("cp.async.wait_group 2;\n" ::: "memory"); }
__device__ __forceinline__ void cp_wait1() { asm volatile("cp.async.wait_group 1;\n" ::: "memory"); }
__device__ __forceinline__ void cp_wait0() { asm volatile("cp.async.wait_group 0;\n" ::: "memory"); }

// ---------------- k0: transpose + convert conv weights to bf16 [tap][ic][oc] ----------------
__global__ void k0_wT(const float* __restrict__ conv_w) {
    int idx = blockIdx.x * blockDim.x + threadIdx.x;
    if (idx < 9 * CC * DD) {
        int oc = idx & 255;
        int ic = (idx >> 8) & 63;
        int tap = idx >> 14;
        g_wT[idx] = __float2bfloat16(conv_w[oc * 576 + ic * 9 + tap]);
    }
}

// ---------------- k1: 3x3 conv + bias + relu -> g_value (NHWC bf16), bf16 wmma ----------------
// Block = (b, h, oc-half): M=128 (w) x N=128 (oc), K=576 (9 taps x 64 ic).
// 128 threads = 4 warps (2 along M x 2 along N); warp tile 64x64. 2 CTAs/SM.
// smem: sA bf16 [3][130][SA_LD=72]     56160 B
//       sB bf16 [3 bufs][64][SB_LD=136] 3x17408 B
//       sBias f32 [128]                 512 B
// Epilogue staging (4 warps x 16KB = 64KB fp32) overlays sA + part of sB0.
#define SA_LD 72
#define SA_ROW (130 * SA_LD)              // 9360 bf16
#define SB_LD 136
#define SB_ELEMS (CC * SB_LD)             // 8704 bf16 = 17408 B
#define SB_OFF_B 56160
#define BIAS_OFF_B (SB_OFF_B + 3 * 17408) // 108384
#define K1_SMEM_BYTES (BIAS_OFF_B + 512)  // 108896

__global__ __launch_bounds__(128, 2) void k1_conv(const float* __restrict__ bev,
                                                  const float* __restrict__ conv_b) {
    extern __shared__ __align__(16) char smraw[];
    __nv_bfloat16* sA = (__nv_bfloat16*)smraw;
    __nv_bfloat16* sB = (__nv_bfloat16*)(smraw + SB_OFF_B);
    float* sBias = (float*)(smraw + BIAS_OFF_B);

    const int tid = threadIdx.x;
    const int h = blockIdx.x;
    const int nh = blockIdx.y;   // oc half: 0 or 1
    const int b = blockIdx.z;

    if (tid < 128) sBias[tid] = conv_b[nh * 128 + tid];

    // ---- async preload taps 0,1 into buffers 0,1 ----
#pragma unroll
    for (int bufi = 0; bufi < 2; bufi++) {
        const __nv_bfloat16* src = g_wT + bufi * (CC * DD) + nh * 128;
        __nv_bfloat16* dst = sB + bufi * SB_ELEMS;
#pragma unroll
        for (int i = 0; i < 8; i++) {
            int c = tid + i * 128;  // 1024 chunks of 8 bf16
            int ic = c >> 4, j = c & 15;
            cp_async16(dst + ic * SB_LD + j * 8, src + ic * DD + j * 8);
        }
        cp_commit();
    }

    // ---- load 3 input rows (halo'd, transposed to [r][wi][ic]) as bf16 ----
    for (int r = 0; r < 3; r++) {
        int gh = h - 1 + r;
        bool rowok = (gh >= 0) && (gh < HH);
        for (int idx = tid; idx < CC * 130; idx += 128) {
            int ic = idx / 130;
            int wi = idx - ic * 130;
            int w = wi - 1;
            float v = 0.f;
            if (rowok && (unsigned)w < (unsigned)WW)
                v = bev[(((size_t)b * CC + ic) * HH + gh) * WW + w];
            sA[r * SA_ROW + wi * SA_LD + ic] = __float2bfloat16(v);
        }
    }

    const int warpId = tid >> 5;
    const int m0 = (warpId & 1) * 64;  // 2 warps along M
    const int n0 = (warpId >> 1) * 64; // 2 warps along N (local within 128)

    wmma::fragment<wmma::accumulator, 16, 16, 16, float> cfr[4][4];
#pragma unroll
    for (int i = 0; i < 4; i++)
#pragma unroll
        for (int j = 0; j < 4; j++) wmma::fill_fragment(cfr[i][j], 0.f);

    for (int tap = 0; tap < 9; tap++) {
        __syncthreads(); // all warps done with tap-1's buffer

        if (tap + 2 <= 8) { // prefetch tap+2 into buffer used by tap-1
            const __nv_bfloat16* src = g_wT + (tap + 2) * (CC * DD) + nh * 128;
            __nv_bfloat16* dst = sB + ((tap + 2) % 3) * SB_ELEMS;
#pragma unroll
            for (int i = 0; i < 8; i++) {
                int c = tid + i * 128;
                int ic = c >> 4, j = c & 15;
                cp_async16(dst + ic * SB_LD + j * 8, src + ic * DD + j * 8);
            }
            cp_commit();
        }
        if (tap < 7) cp_wait2();
        else if (tap == 7) cp_wait1();
        else cp_wait0();

        const int kh = tap / 3, kw = tap - kh * 3;
        const __nv_bfloat16* Abase = sA + kh * SA_ROW + kw * SA_LD;
        const __nv_bfloat16* Bbuf = sB + (tap % 3) * SB_ELEMS;

#pragma unroll
        for (int ks = 0; ks < 4; ks++) { // 64 ic / 16
            wmma::fragment<wmma::matrix_a, 16, 16, 16, __nv_bfloat16, wmma::row_major> afr[4];
            wmma::fragment<wmma::matrix_b, 16, 16, 16, __nv_bfloat16, wmma::row_major> bfr[4];
#pragma unroll
            for (int i = 0; i < 4; i++)
                wmma::load_matrix_sync(afr[i], Abase + (m0 + i * 16) * SA_LD + ks * 16, SA_LD);
#pragma unroll
            for (int j = 0; j < 4; j++)
                wmma::load_matrix_sync(bfr[j], Bbuf + (ks * 16) * SB_LD + n0 + j * 16, SB_LD);
#pragma unroll
            for (int i = 0; i < 4; i++)
#pragma unroll
                for (int j = 0; j < 4; j++)
                    wmma::mma_sync(cfr[i][j], afr[i], bfr[j], cfr[i][j]);
        }
    }

    // ---- epilogue: stage fp32 (overlays sA/sB0), bias+relu, bf16 store ----
    __syncthreads();
    float* stage = (float*)smraw + warpId * 4096; // 64 rows x 64 cols fp32 per warp (64KB total)
#pragma unroll
    for (int i = 0; i < 4; i++)
#pragma unroll
        for (int j = 0; j < 4; j++)
            wmma::store_matrix_sync(stage + i * 16 * 64 + j * 16, cfr[i][j], 64,
                                    wmma::mem_row_major);
    __syncwarp();

    const int lane = tid & 31;
    __nv_bfloat16* gout = g_value + (((size_t)b * HH + h) * WW + m0) * DD + nh * 128 + n0;
#pragma unroll
    for (int it = 0; it < 16; it++) {
        int c = it * 32 + lane;   // 512 chunks of 8 channels (64 rows x 8 chunks)
        int r = c >> 3;
        int c8 = (c & 7) * 8;
        float4 v0 = *(float4*)(stage + r * 64 + c8);
        float4 v1 = *(float4*)(stage + r * 64 + c8 + 4);
        float4 b0 = *(float4*)(sBias + n0 + c8);
        float4 b1 = *(float4*)(sBias + n0 + c8 + 4);
        v0.x = fmaxf(v0.x + b0.x, 0.f); v0.y = fmaxf(v0.y + b0.y, 0.f);
        v0.z = fmaxf(v0.z + b0.z, 0.f); v0.w = fmaxf(v0.w + b0.w, 0.f);
        v1.x = fmaxf(v1.x + b1.x, 0.f); v1.y = fmaxf(v1.y + b1.y, 0.f);
        v1.z = fmaxf(v1.z + b1.z, 0.f); v1.w = fmaxf(v1.w + b1.w, 0.f);
        uint4 u;
        __nv_bfloat162* hp = (__nv_bfloat162*)&u;
        hp[0] = __floats2bfloat162_rn(v0.x, v0.y);
        hp[1] = __floats2bfloat162_rn(v0.z, v0.w);
        hp[2] = __floats2bfloat162_rn(v1.x, v1.y);
        hp[3] = __floats2bfloat162_rn(v1.z, v1.w);
        *(uint4*)(gout + (size_t)r * DD + c8) = u;
    }
}

// ---------------- k2: attention logits + softmax + bilinear gather -> g_ctx ----------------
__global__ __launch_bounds__(256) void k2_sample(const float* __restrict__ queries,
                                                 const float* __restrict__ traj,
                                                 const float* __restrict__ attn_W,
                                                 const float* __restrict__ attn_b) {
    __shared__ float sW[TT * DD];
    __shared__ float sb[TT];
    const int tid = threadIdx.x;
    for (int i = tid; i < TT * DD; i += 256) sW[i] = attn_W[i];
    if (tid < TT) sb[tid] = attn_b[tid];
    __syncthreads();

    const int lane = tid & 31;
    const int g = blockIdx.x * 8 + (tid >> 5);
    const int b = g >> 9;

    const float* q = queries + (size_t)g * DD;
    float a[TT];
#pragma unroll
    for (int t = 0; t < TT; t++) a[t] = 0.f;
    for (int i = lane; i < DD; i += 32) {
        float qv = q[i];
#pragma unroll
        for (int t = 0; t < TT; t++) a[t] += qv * sW[t * DD + i];
    }
#pragma unroll
    for (int t = 0; t < TT; t++) {
#pragma unroll
        for (int o = 16; o > 0; o >>= 1) a[t] += __shfl_xor_sync(0xffffffffu, a[t], o);
        a[t] += sb[t];
    }
    float mx = a[0];
#pragma unroll
    for (int t = 1; t < TT; t++) mx = fmaxf(mx, a[t]);
    float s = 0.f;
#pragma unroll
    for (int t = 0; t < TT; t++) { a[t] = expf(a[t] - mx); s += a[t]; }
    float inv = 1.f / s;
#pragma unroll
    for (int t = 0; t < TT; t++) a[t] *= inv;

    float acc[8];
#pragma unroll
    for (int i = 0; i < 8; i++) acc[i] = 0.f;
    const float* tp = traj + (size_t)g * (TT * 2);
    const __nv_bfloat16* vbase = g_value + (size_t)b * HH * WW * DD;

#pragma unroll
    for (int t = 0; t < TT; t++) {
        float gy = tp[2 * t] * (1.f / 32.f);
        float gx = tp[2 * t + 1] * (1.f / 32.f);
        float x = (gx + 1.f) * (WW * 0.5f) - 0.5f;
        float y = (gy + 1.f) * (HH * 0.5f) - 0.5f;
        float fx0 = floorf(x), fy0 = floorf(y);
        int x0 = (int)fx0, y0 = (int)fy0;
        float wx1 = x - fx0, wx0 = 1.f - wx1;
        float wy1 = y - fy0, wy0 = 1.f - wy1;
        float at = a[t];

        int xs[4] = {x0, x0 + 1, x0, x0 + 1};
        int ys[4] = {y0, y0, y0 + 1, y0 + 1};
        float ws[4] = {at * wx0 * wy0, at * wx1 * wy0, at * wx0 * wy1, at * wx1 * wy1};
#pragma unroll
        for (int cidx = 0; cidx < 4; cidx++) {
            int xi = xs[cidx], yi = ys[cidx];
            if ((unsigned)xi < (unsigned)WW && (unsigned)yi < (unsigned)HH) {
                float w = ws[cidx];
                const uint4* vp = (const uint4*)(vbase + ((size_t)yi * WW + xi) * DD);
                uint4 raw = vp[lane];
                const __nv_bfloat162* hp = (const __nv_bfloat162*)&raw;
                float2 f0 = __bfloat1622float2(hp[0]);
                float2 f1 = __bfloat1622float2(hp[1]);
                float2 f2 = __bfloat1622float2(hp[2]);
                float2 f3 = __bfloat1622float2(hp[3]);
                acc[0] += w * f0.x; acc[1] += w * f0.y;
                acc[2] += w * f1.x; acc[3] += w * f1.y;
                acc[4] += w * f2.x; acc[5] += w * f2.y;
                acc[6] += w * f3.x; acc[7] += w * f3.y;
            }
        }
    }

    float* co = g_ctx + (size_t)g * DD + lane * 8;
    *(float4*)co = make_float4(acc[0], acc[1], acc[2], acc[3]);
    *(float4*)(co + 4) = make_float4(acc[4], acc[5], acc[6], acc[7]);
}

// ---------------- k3: out = ctx @ out_W^T + out_b + queries  (tf32 wmma) ----------------
// 256 blocks x 256 threads; CTA tile 64 rows x 256 oc, K=256 chunked by 32.
// 8 warps: 2 along M (32 rows) x 4 along N (64 oc); warp tile 32x64.
// dyn smem: fill phase sc[64][36] + sw[32][260]; epilogue staging 8 warps x 8KB = 64KB.
#define K3_SC_FLOATS (64 * 36)
#define K3_SW_FLOATS (32 * 260)
#define K3_SMEM_BYTES 65536

__global__ __launch_bounds__(256) void k3_out(const float* __restrict__ queries,
                                              const float* __restrict__ out_W,
                                              const float* __restrict__ out_b,
                                              float* __restrict__ out) {
    extern __shared__ __align__(16) float k3sm[];
    float* sc = k3sm;                 // [64][36]
    float* sw = k3sm + K3_SC_FLOATS;  // [32][260]

    const int tid = threadIdx.x;
    const int row0 = blockIdx.x * 64;
    const int warpId = tid >> 5;
    const int lane = tid & 31;
    const int m0 = (warpId & 1) * 32;   // 2 warps along M
    const int n0 = (warpId >> 1) * 64;  // 4 warps along N

    wmma::fragment<wmma::accumulator, 16, 16, 8, float> cfr[2][4];
#pragma unroll
    for (int i = 0; i < 2; i++)
#pragma unroll
        for (int j = 0; j < 4; j++) wmma::fill_fragment(cfr[i][j], 0.f);

    for (int kc = 0; kc < 8; kc++) {
        __syncthreads();
#pragma unroll
        for (int i = 0; i < 8; i++) { // 64x32 = 2048 elems
            int idx = tid + i * 256;
            int r = idx >> 5, kk = idx & 31;
            sc[r * 36 + kk] = wmma::__float_to_tf32(
                g_ctx[(size_t)(row0 + r) * DD + kc * 32 + kk]);
        }
        for (int idx = tid; idx < 256 * 32; idx += 256) {
            int oc = idx >> 5, kk = idx & 31;
            sw[kk * 260 + oc] = wmma::__float_to_tf32(
                out_W[(size_t)oc * DD + kc * 32 + kk]);
        }
        __syncthreads();

#pragma unroll
        for (int ks = 0; ks < 4; ks++) { // 32 k / 8
            wmma::fragment<wmma::matrix_a, 16, 16, 8, wmma::precision::tf32, wmma::row_major> afr[2];
            wmma::fragment<wmma::matrix_b, 16, 16, 8, wmma::precision::tf32, wmma::row_major> bfr[4];
#pragma unroll
            for (int i = 0; i < 2; i++)
                wmma::load_matrix_sync(afr[i], sc + (m0 + i * 16) * 36 + ks * 8, 36);
#pragma unroll
            for (int j = 0; j < 4; j++)
                wmma::load_matrix_sync(bfr[j], sw + (ks * 8) * 260 + n0 + j * 16, 260);
#pragma unroll
            for (int i = 0; i < 2; i++)
#pragma unroll
                for (int j = 0; j < 4; j++)
                    wmma::mma_sync(cfr[i][j], afr[i], bfr[j], cfr[i][j]);
        }
    }

    // ---- epilogue: stage, + bias + queries, store ----
    __syncthreads();
    float* stage = k3sm + warpId * 2048; // 32 rows x 64 cols per warp
#pragma unroll
    for (int i = 0; i < 2; i++)
#pragma unroll
        for (int j = 0; j < 4; j++)
            wmma::store_matrix_sync(stage + i * 16 * 64 + j * 16, cfr[i][j], 64,
                                    wmma::mem_row_major);
    __syncwarp();

#pragma unroll
    for (int it = 0; it < 16; it++) {
        int c = it * 32 + lane;  // 512 chunks of 4 cols (32 rows x 16 chunks)
        int r = c >> 4;
        int c4 = (c & 15) * 4;
        int rg = row0 + m0 + r;
        float4 v = *(float4*)(stage + r * 64 + c4);
        float4 bb4 = *(const float4*)&out_b[n0 + c4];
        float4 qv = *(const float4*)&queries[(size_t)rg * DD + n0 + c4];
        v.x += bb4.x + qv.x;
        v.y += bb4.y + qv.y;
        v.z += bb4.z + qv.z;
        v.w += bb4.w + qv.w;
        *(float4*)&out[(size_t)rg * DD + n0 + c4] = v;
    }
}

// ---------------- launch ----------------
extern "C" void kernel_launch(void* const* d_in, const int* in_sizes, int n_in,
                              void* d_out, int out_size) {
    const float* queries = (const float*)d_in[0];
    const float* traj = (const float*)d_in[1];
    const float* bev = (const float*)d_in[2];
    const float* conv_w = (const float*)d_in[3];
    const float* conv_b = (const float*)d_in[4];
    const float* attn_W = (const float*)d_in[5];
    const float* attn_b = (const float*)d_in[6];
    const float* out_W = (const float*)d_in[7];
    const float* out_b = (const float*)d_in[8];
    float* out = (float*)d_out;

    cudaFuncSetAttribute(k1_conv, cudaFuncAttributeMaxDynamicSharedMemorySize, K1_SMEM_BYTES);
    cudaFuncSetAttribute(k3_out, cudaFuncAttributeMaxDynamicSharedMemorySize, K3_SMEM_BYTES);

    k0_wT<<<(9 * CC * DD + 255) / 256, 256>>>(conv_w);
    k1_conv<<<dim3(HH, 2, BB), 128, K1_SMEM_BYTES>>>(bev, conv_b);
    k2_sample<<<(BB * KK) / 8, 256>>>(queries, traj, attn_W, attn_b);
    k3_out<<<(BB * KK) / 64, 256, K3_SMEM_BYTES>>>(queries, out_W, out_b, out);
}

// round 10
// speedup vs baseline: 1.1043x; 1.1043x over previous
#include <cuda_runtime.h>
#include <cuda_bf16.h>
#include <mma.h>
#include <cstdint>

using namespace nvcuda;

// Shapes (fixed by problem)
#define BB 32
#define KK 512
#define TT 8
#define DD 256
#define CC 64
#define HH 128
#define WW 128

// ---------------- scratch (static device globals; no cudaMalloc) ----------------
__device__ __align__(16) __nv_bfloat16 g_value[(size_t)BB * HH * WW * DD]; // 256MB NHWC bf16
__device__ __align__(16) float g_ctx[(size_t)BB * KK * DD];                // 16MB
__device__ __align__(16) __nv_bfloat16 g_wT[9 * CC * DD];                  // [tap][ic][oc] bf16

// ---------------- cp.async helpers ----------------
__device__ __forceinline__ void cp_async16(void* smem_dst, const void* gsrc) {
    unsigned int s = (unsigned int)__cvta_generic_to_shared(smem_dst);
    asm volatile("cp.async.cg.shared.global [%0], [%1], 16;\n" ::"r"(s), "l"(gsrc));
}
__device__ __forceinline__ void cp_commit() { asm volatile("cp.async.commit_group;\n"); }
__device__ __forceinline__ void cp_wait2() { asm volatile("cp.async.wait_group 2;\n" ::: "memory"); }
__device__ __forceinline__ void cp_wait1() { asm volatile("cp.async.wait_group 1;\n" ::: "memory"); }
__device__ __forceinline__ void cp_wait0() { asm volatile("cp.async.wait_group 0;\n" ::: "memory"); }

// ---------------- k0: transpose + convert conv weights to bf16 [tap][ic][oc] ----------------
__global__ void k0_wT(const float* __restrict__ conv_w) {
    int idx = blockIdx.x * blockDim.x + threadIdx.x;
    if (idx < 9 * CC * DD) {
        int oc = idx & 255;
        int ic = (idx >> 8) & 63;
        int tap = idx >> 14;
        g_wT[idx] = __float2bfloat16(conv_w[oc * 576 + ic * 9 + tap]);
    }
}

// ---------------- k1: 3x3 conv + bias + relu -> g_value (NHWC bf16), bf16 wmma ----------------
// (R6 best-measured config) Block = (b, h, oc-half): M=128 x N=128, K=576.
// 256 threads = 8 warps (4M x 2N); warp tile 32x64. 2 CTAs/SM.
#define SA_LD 72
#define SA_ROW (130 * SA_LD)              // 9360 bf16
#define SB_LD 136
#define SB_ELEMS (CC * SB_LD)             // 8704 bf16 = 17408 B
#define SB_OFF_B 56160
#define BIAS_OFF_B (SB_OFF_B + 3 * 17408) // 108384
#define K1_SMEM_BYTES (BIAS_OFF_B + 512)  // 108896

__global__ __launch_bounds__(256, 2) void k1_conv(const float* __restrict__ bev,
                                                  const float* __restrict__ conv_b) {
    extern __shared__ __align__(16) char smraw[];
    __nv_bfloat16* sA = (__nv_bfloat16*)smraw;
    __nv_bfloat16* sB = (__nv_bfloat16*)(smraw + SB_OFF_B);
    float* sBias = (float*)(smraw + BIAS_OFF_B);

    const int tid = threadIdx.x;
    const int h = blockIdx.x;
    const int nh = blockIdx.y;   // oc half: 0 or 1
    const int b = blockIdx.z;

    if (tid < 128) sBias[tid] = conv_b[nh * 128 + tid];

    // ---- async preload taps 0,1 into buffers 0,1 ----
#pragma unroll
    for (int bufi = 0; bufi < 2; bufi++) {
        const __nv_bfloat16* src = g_wT + bufi * (CC * DD) + nh * 128;
        __nv_bfloat16* dst = sB + bufi * SB_ELEMS;
#pragma unroll
        for (int i = 0; i < 4; i++) {
            int c = tid + i * 256;  // 1024 chunks of 8 bf16
            int ic = c >> 4, j = c & 15;
            cp_async16(dst + ic * SB_LD + j * 8, src + ic * DD + j * 8);
        }
        cp_commit();
    }

    // ---- load 3 input rows (halo'd, transposed to [r][wi][ic]) as bf16 ----
    for (int r = 0; r < 3; r++) {
        int gh = h - 1 + r;
        bool rowok = (gh >= 0) && (gh < HH);
        for (int idx = tid; idx < CC * 130; idx += 256) {
            int ic = idx / 130;
            int wi = idx - ic * 130;
            int w = wi - 1;
            float v = 0.f;
            if (rowok && (unsigned)w < (unsigned)WW)
                v = bev[(((size_t)b * CC + ic) * HH + gh) * WW + w];
            sA[r * SA_ROW + wi * SA_LD + ic] = __float2bfloat16(v);
        }
    }

    const int warpId = tid >> 5;
    const int m0 = (warpId >> 1) * 32; // 4 warps along M
    const int n0 = (warpId & 1) * 64;  // 2 warps along N (local within 128)

    wmma::fragment<wmma::accumulator, 16, 16, 16, float> cfr[2][4];
#pragma unroll
    for (int i = 0; i < 2; i++)
#pragma unroll
        for (int j = 0; j < 4; j++) wmma::fill_fragment(cfr[i][j], 0.f);

    for (int tap = 0; tap < 9; tap++) {
        __syncthreads(); // all warps done with tap-1's buffer

        if (tap + 2 <= 8) { // prefetch tap+2 into buffer used by tap-1
            const __nv_bfloat16* src = g_wT + (tap + 2) * (CC * DD) + nh * 128;
            __nv_bfloat16* dst = sB + ((tap + 2) % 3) * SB_ELEMS;
#pragma unroll
            for (int i = 0; i < 4; i++) {
                int c = tid + i * 256;
                int ic = c >> 4, j = c & 15;
                cp_async16(dst + ic * SB_LD + j * 8, src + ic * DD + j * 8);
            }
            cp_commit();
        }
        if (tap < 7) cp_wait2();
        else if (tap == 7) cp_wait1();
        else cp_wait0();

        const int kh = tap / 3, kw = tap - kh * 3;
        const __nv_bfloat16* Abase = sA + kh * SA_ROW + kw * SA_LD;
        const __nv_bfloat16* Bbuf = sB + (tap % 3) * SB_ELEMS;

#pragma unroll
        for (int ks = 0; ks < 4; ks++) { // 64 ic / 16
            wmma::fragment<wmma::matrix_a, 16, 16, 16, __nv_bfloat16, wmma::row_major> afr[2];
            wmma::fragment<wmma::matrix_b, 16, 16, 16, __nv_bfloat16, wmma::row_major> bfr[4];
#pragma unroll
            for (int i = 0; i < 2; i++)
                wmma::load_matrix_sync(afr[i], Abase + (m0 + i * 16) * SA_LD + ks * 16, SA_LD);
#pragma unroll
            for (int j = 0; j < 4; j++)
                wmma::load_matrix_sync(bfr[j], Bbuf + (ks * 16) * SB_LD + n0 + j * 16, SB_LD);
#pragma unroll
            for (int i = 0; i < 2; i++)
#pragma unroll
                for (int j = 0; j < 4; j++)
                    wmma::mma_sync(cfr[i][j], afr[i], bfr[j], cfr[i][j]);
        }
    }

    // ---- epilogue: stage fp32 (overlays sA/sB0), bias+relu, bf16 store ----
    __syncthreads();
    float* stage = (float*)smraw + warpId * 2048; // 32 rows x 64 cols fp32 per warp
#pragma unroll
    for (int i = 0; i < 2; i++)
#pragma unroll
        for (int j = 0; j < 4; j++)
            wmma::store_matrix_sync(stage + i * 16 * 64 + j * 16, cfr[i][j], 64,
                                    wmma::mem_row_major);
    __syncwarp();

    const int lane = tid & 31;
    __nv_bfloat16* gout = g_value + (((size_t)b * HH + h) * WW + m0) * DD + nh * 128 + n0;
#pragma unroll
    for (int it = 0; it < 8; it++) {
        int c = it * 32 + lane;   // 256 chunks of 8 channels (32 rows x 8 chunks)
        int r = c >> 3;
        int c8 = (c & 7) * 8;
        float4 v0 = *(float4*)(stage + r * 64 + c8);
        float4 v1 = *(float4*)(stage + r * 64 + c8 + 4);
        float4 b0 = *(float4*)(sBias + n0 + c8);
        float4 b1 = *(float4*)(sBias + n0 + c8 + 4);
        v0.x = fmaxf(v0.x + b0.x, 0.f); v0.y = fmaxf(v0.y + b0.y, 0.f);
        v0.z = fmaxf(v0.z + b0.z, 0.f); v0.w = fmaxf(v0.w + b0.w, 0.f);
        v1.x = fmaxf(v1.x + b1.x, 0.f); v1.y = fmaxf(v1.y + b1.y, 0.f);
        v1.z = fmaxf(v1.z + b1.z, 0.f); v1.w = fmaxf(v1.w + b1.w, 0.f);
        uint4 u;
        __nv_bfloat162* hp = (__nv_bfloat162*)&u;
        hp[0] = __floats2bfloat162_rn(v0.x, v0.y);
        hp[1] = __floats2bfloat162_rn(v0.z, v0.w);
        hp[2] = __floats2bfloat162_rn(v1.x, v1.y);
        hp[3] = __floats2bfloat162_rn(v1.z, v1.w);
        *(uint4*)(gout + (size_t)r * DD + c8) = u;
    }
}

// ---------------- k2: attention logits + softmax + bilinear gather -> g_ctx ----------------
__global__ __launch_bounds__(256) void k2_sample(const float* __restrict__ queries,
                                                 const float* __restrict__ traj,
                                                 const float* __restrict__ attn_W,
                                                 const float* __restrict__ attn_b) {
    __shared__ float sW[TT * DD];
    __shared__ float sb[TT];
    const int tid = threadIdx.x;
    for (int i = tid; i < TT * DD; i += 256) sW[i] = attn_W[i];
    if (tid < TT) sb[tid] = attn_b[tid];
    __syncthreads();

    const int lane = tid & 31;
    const int g = blockIdx.x * 8 + (tid >> 5);
    const int b = g >> 9;

    const float* q = queries + (size_t)g * DD;
    float a[TT];
#pragma unroll
    for (int t = 0; t < TT; t++) a[t] = 0.f;
    for (int i = lane; i < DD; i += 32) {
        float qv = q[i];
#pragma unroll
        for (int t = 0; t < TT; t++) a[t] += qv * sW[t * DD + i];
    }
#pragma unroll
    for (int t = 0; t < TT; t++) {
#pragma unroll
        for (int o = 16; o > 0; o >>= 1) a[t] += __shfl_xor_sync(0xffffffffu, a[t], o);
        a[t] += sb[t];
    }
    float mx = a[0];
#pragma unroll
    for (int t = 1; t < TT; t++) mx = fmaxf(mx, a[t]);
    float s = 0.f;
#pragma unroll
    for (int t = 0; t < TT; t++) { a[t] = expf(a[t] - mx); s += a[t]; }
    float inv = 1.f / s;
#pragma unroll
    for (int t = 0; t < TT; t++) a[t] *= inv;

    float acc[8];
#pragma unroll
    for (int i = 0; i < 8; i++) acc[i] = 0.f;
    const float* tp = traj + (size_t)g * (TT * 2);
    const __nv_bfloat16* vbase = g_value + (size_t)b * HH * WW * DD;

#pragma unroll
    for (int t = 0; t < TT; t++) {
        float gy = tp[2 * t] * (1.f / 32.f);
        float gx = tp[2 * t + 1] * (1.f / 32.f);
        float x = (gx + 1.f) * (WW * 0.5f) - 0.5f;
        float y = (gy + 1.f) * (HH * 0.5f) - 0.5f;
        float fx0 = floorf(x), fy0 = floorf(y);
        int x0 = (int)fx0, y0 = (int)fy0;
        float wx1 = x - fx0, wx0 = 1.f - wx1;
        float wy1 = y - fy0, wy0 = 1.f - wy1;
        float at = a[t];

        int xs[4] = {x0, x0 + 1, x0, x0 + 1};
        int ys[4] = {y0, y0, y0 + 1, y0 + 1};
        float ws[4] = {at * wx0 * wy0, at * wx1 * wy0, at * wx0 * wy1, at * wx1 * wy1};
#pragma unroll
        for (int cidx = 0; cidx < 4; cidx++) {
            int xi = xs[cidx], yi = ys[cidx];
            if ((unsigned)xi < (unsigned)WW && (unsigned)yi < (unsigned)HH) {
                float w = ws[cidx];
                const uint4* vp = (const uint4*)(vbase + ((size_t)yi * WW + xi) * DD);
                uint4 raw = vp[lane];
                const __nv_bfloat162* hp = (const __nv_bfloat162*)&raw;
                float2 f0 = __bfloat1622float2(hp[0]);
                float2 f1 = __bfloat1622float2(hp[1]);
                float2 f2 = __bfloat1622float2(hp[2]);
                float2 f3 = __bfloat1622float2(hp[3]);
                acc[0] += w * f0.x; acc[1] += w * f0.y;
                acc[2] += w * f1.x; acc[3] += w * f1.y;
                acc[4] += w * f2.x; acc[5] += w * f2.y;
                acc[6] += w * f3.x; acc[7] += w * f3.y;
            }
        }
    }

    float* co = g_ctx + (size_t)g * DD + lane * 8;
    *(float4*)co = make_float4(acc[0], acc[1], acc[2], acc[3]);
    *(float4*)(co + 4) = make_float4(acc[4], acc[5], acc[6], acc[7]);
}

// ---------------- k3: out = ctx @ out_W^T + out_b + queries  (tf32 wmma, v3) ----------------
// grid 512, block 256 (8 warps = 2M x 4N); CTA tile M=32 rows x N=256 oc; K chunks of 32.
// Double-buffered cp.async: sc[32][40] fp32 (ctx), sw[256][32] fp32 (W rows verbatim,
// consumed as col-major B fragments).
#define K3_SC_LD 40
#define K3_BUF_FLOATS (32 * K3_SC_LD + 256 * 32)  // 1280 + 8192 = 9472
#define K3_SMEM_BYTES (2 * K3_BUF_FLOATS * 4)     // 75776

__global__ __launch_bounds__(256) void k3_out(const float* __restrict__ queries,
                                              const float* __restrict__ out_W,
                                              const float* __restrict__ out_b,
                                              float* __restrict__ out) {
    extern __shared__ __align__(16) float k3sm[];
    const int tid = threadIdx.x;
    const int row0 = blockIdx.x * 32;
    const int warpId = tid >> 5;
    const int lane = tid & 31;
    const int m0 = (warpId & 1) * 16;   // 2 warps along M
    const int n0 = (warpId >> 1) * 64;  // 4 warps along N

    // prefetch of chunk kc into buffer buf
    auto prefetch = [&](int kc, int buf) {
        float* sc = k3sm + buf * K3_BUF_FLOATS;
        float* sw = sc + 32 * K3_SC_LD;
        // ctx: 32 rows x 32 k = 4KB -> 256 x 16B
        {
            int r = tid >> 3, j = tid & 7;
            cp_async16(sc + r * K3_SC_LD + j * 4,
                       g_ctx + (size_t)(row0 + r) * DD + kc * 32 + j * 4);
        }
        // W: 256 oc x 32 k = 32KB -> 2048 x 16B
#pragma unroll
        for (int i = 0; i < 8; i++) {
            int c = tid + i * 256;
            int oc = c >> 3, j = c & 7;
            cp_async16(sw + oc * 32 + j * 4, out_W + (size_t)oc * DD + kc * 32 + j * 4);
        }
        cp_commit();
    };

    prefetch(0, 0);

    wmma::fragment<wmma::accumulator, 16, 16, 8, float> cfr[4];
#pragma unroll
    for (int j = 0; j < 4; j++) wmma::fill_fragment(cfr[j], 0.f);

    for (int kc = 0; kc < 8; kc++) {
        if (kc + 1 < 8) {
            prefetch(kc + 1, (kc + 1) & 1);
            cp_wait1();
        } else {
            cp_wait0();
        }
        __syncthreads();

        const float* sc = k3sm + (kc & 1) * K3_BUF_FLOATS;
        const float* sw = sc + 32 * K3_SC_LD;

#pragma unroll
        for (int ks = 0; ks < 4; ks++) { // 32 k / 8
            wmma::fragment<wmma::matrix_a, 16, 16, 8, wmma::precision::tf32, wmma::row_major> afr;
            wmma::fragment<wmma::matrix_b, 16, 16, 8, wmma::precision::tf32, wmma::col_major> bfr[4];
            wmma::load_matrix_sync(afr, sc + m0 * K3_SC_LD + ks * 8, K3_SC_LD);
#pragma unroll
            for (int e = 0; e < afr.num_elements; e++) afr.x[e] = wmma::__float_to_tf32(afr.x[e]);
#pragma unroll
            for (int j = 0; j < 4; j++) {
                // B col-major: element (k, n) at sw[n*32 + k]
                wmma::load_matrix_sync(bfr[j], sw + (n0 + j * 16) * 32 + ks * 8, 32);
#pragma unroll
                for (int e = 0; e < bfr[j].num_elements; e++)
                    bfr[j].x[e] = wmma::__float_to_tf32(bfr[j].x[e]);
            }
#pragma unroll
            for (int j = 0; j < 4; j++) wmma::mma_sync(cfr[j], afr, bfr[j], cfr[j]);
        }
        __syncthreads(); // done reading this buffer before it is prefetch-overwritten
    }

    // ---- epilogue: stage, + bias + queries, store ----
    float* stage = k3sm + warpId * 1024; // 16 rows x 64 cols per warp
#pragma unroll
    for (int j = 0; j < 4; j++)
        wmma::store_matrix_sync(stage + j * 16, cfr[j], 64, wmma::mem_row_major);
    __syncwarp();

#pragma unroll
    for (int it = 0; it < 8; it++) {
        int c = it * 32 + lane;  // 256 chunks of 4 cols (16 rows x 16 chunks)
        int r = c >> 4;
        int c4 = (c & 15) * 4;
        int rg = row0 + m0 + r;
        float4 v = *(float4*)(stage + r * 64 + c4);
        float4 bb4 = *(const float4*)&out_b[n0 + c4];
        float4 qv = *(const float4*)&queries[(size_t)rg * DD + n0 + c4];
        v.x += bb4.x + qv.x;
        v.y += bb4.y + qv.y;
        v.z += bb4.z + qv.z;
        v.w += bb4.w + qv.w;
        *(float4*)&out[(size_t)rg * DD + n0 + c4] = v;
    }
}

// ---------------- launch ----------------
extern "C" void kernel_launch(void* const* d_in, const int* in_sizes, int n_in,
                              void* d_out, int out_size) {
    const float* queries = (const float*)d_in[0];
    const float* traj = (const float*)d_in[1];
    const float* bev = (const float*)d_in[2];
    const float* conv_w = (const float*)d_in[3];
    const float* conv_b = (const float*)d_in[4];
    const float* attn_W = (const float*)d_in[5];
    const float* attn_b = (const float*)d_in[6];
    const float* out_W = (const float*)d_in[7];
    const float* out_b = (const float*)d_in[8];
    float* out = (float*)d_out;

    cudaFuncSetAttribute(k1_conv, cudaFuncAttributeMaxDynamicSharedMemorySize, K1_SMEM_BYTES);
    cudaFuncSetAttribute(k3_out, cudaFuncAttributeMaxDynamicSharedMemorySize, K3_SMEM_BYTES);

    k0_wT<<<(9 * CC * DD + 255) / 256, 256>>>(conv_w);
    k1_conv<<<dim3(HH, 2, BB), 256, K1_SMEM_BYTES>>>(bev, conv_b);
    k2_sample<<<(BB * KK) / 8, 256>>>(queries, traj, attn_W, attn_b);
    k3_out<<<(BB * KK) / 32, 256, K3_SMEM_BYTES>>>(queries, out_W, out_b, out);
}

// round 12
// speedup vs baseline: 1.1330x; 1.0260x over previous
#include <cuda_runtime.h>
#include <cuda_bf16.h>
#include <mma.h>
#include <cstdint>

using namespace nvcuda;

// Shapes (fixed by problem)
#define BB 32
#define KK 512
#define TT 8
#define DD 256
#define CC 64
#define HH 128
#define WW 128

// ---------------- scratch (static device globals; no cudaMalloc) ----------------
__device__ __align__(16) __nv_bfloat16 g_value[(size_t)BB * HH * WW * DD]; // 256MB NHWC bf16
__device__ __align__(16) float g_ctx[(size_t)BB * KK * DD];                // 16MB
__device__ __align__(16) __nv_bfloat16 g_wT[9 * CC * DD];                  // [tap][ic][oc] bf16

// ---------------- cp.async helpers ----------------
__device__ __forceinline__ void cp_async16(void* smem_dst, const void* gsrc) {
    unsigned int s = (unsigned int)__cvta_generic_to_shared(smem_dst);
    asm volatile("cp.async.cg.shared.global [%0], [%1], 16;\n" ::"r"(s), "l"(gsrc));
}
__device__ __forceinline__ void cp_commit() { asm volatile("cp.async.commit_group;\n"); }
__device__ __forceinline__ void cp_wait2() { asm volatile("cp.async.wait_group 2;\n" ::: "memory"); }
__device__ __forceinline__ void cp_wait1() { asm volatile("cp.async.wait_group 1;\n" ::: "memory"); }
__device__ __forceinline__ void cp_wait0() { asm volatile("cp.async.wait_group 0;\n" ::: "memory"); }

// ---------------- k0: transpose + convert conv weights to bf16 [tap][ic][oc] ----------------
__global__ void k0_wT(const float* __restrict__ conv_w) {
    int idx = blockIdx.x * blockDim.x + threadIdx.x;
    if (idx < 9 * CC * DD) {
        int oc = idx & 255;
        int ic = (idx >> 8) & 63;
        int tap = idx >> 14;
        g_wT[idx] = __float2bfloat16(conv_w[oc * 576 + ic * 9 + tap]);
    }
}

// ---------------- k1: 3x3 conv + bias + relu -> g_value (NHWC bf16), bf16 wmma ----------------
// (R6 best-measured config) Block = (b, h, oc-half): M=128 x N=128, K=576.
// 256 threads = 8 warps (4M x 2N); warp tile 32x64. 2 CTAs/SM.
#define SA_LD 72
#define SA_ROW (130 * SA_LD)              // 9360 bf16
#define SB_LD 136
#define SB_ELEMS (CC * SB_LD)             // 8704 bf16 = 17408 B
#define SB_OFF_B 56160
#define BIAS_OFF_B (SB_OFF_B + 3 * 17408) // 108384
#define K1_SMEM_BYTES (BIAS_OFF_B + 512)  // 108896

__global__ __launch_bounds__(256, 2) void k1_conv(const float* __restrict__ bev,
                                                  const float* __restrict__ conv_b) {
    extern __shared__ __align__(16) char smraw[];
    __nv_bfloat16* sA = (__nv_bfloat16*)smraw;
    __nv_bfloat16* sB = (__nv_bfloat16*)(smraw + SB_OFF_B);
    float* sBias = (float*)(smraw + BIAS_OFF_B);

    const int tid = threadIdx.x;
    const int h = blockIdx.x;
    const int nh = blockIdx.y;   // oc half: 0 or 1
    const int b = blockIdx.z;

    if (tid < 128) sBias[tid] = conv_b[nh * 128 + tid];

    // ---- async preload taps 0,1 into buffers 0,1 ----
#pragma unroll
    for (int bufi = 0; bufi < 2; bufi++) {
        const __nv_bfloat16* src = g_wT + bufi * (CC * DD) + nh * 128;
        __nv_bfloat16* dst = sB + bufi * SB_ELEMS;
#pragma unroll
        for (int i = 0; i < 4; i++) {
            int c = tid + i * 256;  // 1024 chunks of 8 bf16
            int ic = c >> 4, j = c & 15;
            cp_async16(dst + ic * SB_LD + j * 8, src + ic * DD + j * 8);
        }
        cp_commit();
    }

    // ---- load 3 input rows (halo'd, transposed to [r][wi][ic]) as bf16 ----
    for (int r = 0; r < 3; r++) {
        int gh = h - 1 + r;
        bool rowok = (gh >= 0) && (gh < HH);
        for (int idx = tid; idx < CC * 130; idx += 256) {
            int ic = idx / 130;
            int wi = idx - ic * 130;
            int w = wi - 1;
            float v = 0.f;
            if (rowok && (unsigned)w < (unsigned)WW)
                v = bev[(((size_t)b * CC + ic) * HH + gh) * WW + w];
            sA[r * SA_ROW + wi * SA_LD + ic] = __float2bfloat16(v);
        }
    }

    const int warpId = tid >> 5;
    const int m0 = (warpId >> 1) * 32; // 4 warps along M
    const int n0 = (warpId & 1) * 64;  // 2 warps along N (local within 128)

    wmma::fragment<wmma::accumulator, 16, 16, 16, float> cfr[2][4];
#pragma unroll
    for (int i = 0; i < 2; i++)
#pragma unroll
        for (int j = 0; j < 4; j++) wmma::fill_fragment(cfr[i][j], 0.f);

    for (int tap = 0; tap < 9; tap++) {
        __syncthreads(); // all warps done with tap-1's buffer

        if (tap + 2 <= 8) { // prefetch tap+2 into buffer used by tap-1
            const __nv_bfloat16* src = g_wT + (tap + 2) * (CC * DD) + nh * 128;
            __nv_bfloat16* dst = sB + ((tap + 2) % 3) * SB_ELEMS;
#pragma unroll
            for (int i = 0; i < 4; i++) {
                int c = tid + i * 256;
                int ic = c >> 4, j = c & 15;
                cp_async16(dst + ic * SB_LD + j * 8, src + ic * DD + j * 8);
            }
            cp_commit();
        }
        if (tap < 7) cp_wait2();
        else if (tap == 7) cp_wait1();
        else cp_wait0();

        const int kh = tap / 3, kw = tap - kh * 3;
        const __nv_bfloat16* Abase = sA + kh * SA_ROW + kw * SA_LD;
        const __nv_bfloat16* Bbuf = sB + (tap % 3) * SB_ELEMS;

#pragma unroll
        for (int ks = 0; ks < 4; ks++) { // 64 ic / 16
            wmma::fragment<wmma::matrix_a, 16, 16, 16, __nv_bfloat16, wmma::row_major> afr[2];
            wmma::fragment<wmma::matrix_b, 16, 16, 16, __nv_bfloat16, wmma::row_major> bfr[4];
#pragma unroll
            for (int i = 0; i < 2; i++)
                wmma::load_matrix_sync(afr[i], Abase + (m0 + i * 16) * SA_LD + ks * 16, SA_LD);
#pragma unroll
            for (int j = 0; j < 4; j++)
                wmma::load_matrix_sync(bfr[j], Bbuf + (ks * 16) * SB_LD + n0 + j * 16, SB_LD);
#pragma unroll
            for (int i = 0; i < 2; i++)
#pragma unroll
                for (int j = 0; j < 4; j++)
                    wmma::mma_sync(cfr[i][j], afr[i], bfr[j], cfr[i][j]);
        }
    }

    // ---- epilogue: stage fp32 (overlays sA/sB0), bias+relu, bf16 store ----
    __syncthreads();
    float* stage = (float*)smraw + warpId * 2048; // 32 rows x 64 cols fp32 per warp
#pragma unroll
    for (int i = 0; i < 2; i++)
#pragma unroll
        for (int j = 0; j < 4; j++)
            wmma::store_matrix_sync(stage + i * 16 * 64 + j * 16, cfr[i][j], 64,
                                    wmma::mem_row_major);
    __syncwarp();

    const int lane = tid & 31;
    __nv_bfloat16* gout = g_value + (((size_t)b * HH + h) * WW + m0) * DD + nh * 128 + n0;
#pragma unroll
    for (int it = 0; it < 8; it++) {
        int c = it * 32 + lane;   // 256 chunks of 8 channels (32 rows x 8 chunks)
        int r = c >> 3;
        int c8 = (c & 7) * 8;
        float4 v0 = *(float4*)(stage + r * 64 + c8);
        float4 v1 = *(float4*)(stage + r * 64 + c8 + 4);
        float4 b0 = *(float4*)(sBias + n0 + c8);
        float4 b1 = *(float4*)(sBias + n0 + c8 + 4);
        v0.x = fmaxf(v0.x + b0.x, 0.f); v0.y = fmaxf(v0.y + b0.y, 0.f);
        v0.z = fmaxf(v0.z + b0.z, 0.f); v0.w = fmaxf(v0.w + b0.w, 0.f);
        v1.x = fmaxf(v1.x + b1.x, 0.f); v1.y = fmaxf(v1.y + b1.y, 0.f);
        v1.z = fmaxf(v1.z + b1.z, 0.f); v1.w = fmaxf(v1.w + b1.w, 0.f);
        uint4 u;
        __nv_bfloat162* hp = (__nv_bfloat162*)&u;
        hp[0] = __floats2bfloat162_rn(v0.x, v0.y);
        hp[1] = __floats2bfloat162_rn(v0.z, v0.w);
        hp[2] = __floats2bfloat162_rn(v1.x, v1.y);
        hp[3] = __floats2bfloat162_rn(v1.z, v1.w);
        *(uint4*)(gout + (size_t)r * DD + c8) = u;
    }
}

// ---------------- k2: attention logits + softmax + bilinear gather -> g_ctx ----------------
__global__ __launch_bounds__(256) void k2_sample(const float* __restrict__ queries,
                                                 const float* __restrict__ traj,
                                                 const float* __restrict__ attn_W,
                                                 const float* __restrict__ attn_b) {
    __shared__ float sW[TT * DD];
    __shared__ float sb[TT];
    const int tid = threadIdx.x;
    for (int i = tid; i < TT * DD; i += 256) sW[i] = attn_W[i];
    if (tid < TT) sb[tid] = attn_b[tid];
    __syncthreads();

    const int lane = tid & 31;
    const int g = blockIdx.x * 8 + (tid >> 5);
    const int b = g >> 9;

    const float* q = queries + (size_t)g * DD;
    float a[TT];
#pragma unroll
    for (int t = 0; t < TT; t++) a[t] = 0.f;
    for (int i = lane; i < DD; i += 32) {
        float qv = q[i];
#pragma unroll
        for (int t = 0; t < TT; t++) a[t] += qv * sW[t * DD + i];
    }
#pragma unroll
    for (int t = 0; t < TT; t++) {
#pragma unroll
        for (int o = 16; o > 0; o >>= 1) a[t] += __shfl_xor_sync(0xffffffffu, a[t], o);
        a[t] += sb[t];
    }
    float mx = a[0];
#pragma unroll
    for (int t = 1; t < TT; t++) mx = fmaxf(mx, a[t]);
    float s = 0.f;
#pragma unroll
    for (int t = 0; t < TT; t++) { a[t] = expf(a[t] - mx); s += a[t]; }
    float inv = 1.f / s;
#pragma unroll
    for (int t = 0; t < TT; t++) a[t] *= inv;

    float acc[8];
#pragma unroll
    for (int i = 0; i < 8; i++) acc[i] = 0.f;
    const float* tp = traj + (size_t)g * (TT * 2);
    const __nv_bfloat16* vbase = g_value + (size_t)b * HH * WW * DD;

#pragma unroll
    for (int t = 0; t < TT; t++) {
        float gy = tp[2 * t] * (1.f / 32.f);
        float gx = tp[2 * t + 1] * (1.f / 32.f);
        float x = (gx + 1.f) * (WW * 0.5f) - 0.5f;
        float y = (gy + 1.f) * (HH * 0.5f) - 0.5f;
        float fx0 = floorf(x), fy0 = floorf(y);
        int x0 = (int)fx0, y0 = (int)fy0;
        float wx1 = x - fx0, wx0 = 1.f - wx1;
        float wy1 = y - fy0, wy0 = 1.f - wy1;
        float at = a[t];

        int xs[4] = {x0, x0 + 1, x0, x0 + 1};
        int ys[4] = {y0, y0, y0 + 1, y0 + 1};
        float ws[4] = {at * wx0 * wy0, at * wx1 * wy0, at * wx0 * wy1, at * wx1 * wy1};
#pragma unroll
        for (int cidx = 0; cidx < 4; cidx++) {
            int xi = xs[cidx], yi = ys[cidx];
            if ((unsigned)xi < (unsigned)WW && (unsigned)yi < (unsigned)HH) {
                float w = ws[cidx];
                const uint4* vp = (const uint4*)(vbase + ((size_t)yi * WW + xi) * DD);
                uint4 raw = vp[lane];
                const __nv_bfloat162* hp = (const __nv_bfloat162*)&raw;
                float2 f0 = __bfloat1622float2(hp[0]);
                float2 f1 = __bfloat1622float2(hp[1]);
                float2 f2 = __bfloat1622float2(hp[2]);
                float2 f3 = __bfloat1622float2(hp[3]);
                acc[0] += w * f0.x; acc[1] += w * f0.y;
                acc[2] += w * f1.x; acc[3] += w * f1.y;
                acc[4] += w * f2.x; acc[5] += w * f2.y;
                acc[6] += w * f3.x; acc[7] += w * f3.y;
            }
        }
    }

    float* co = g_ctx + (size_t)g * DD + lane * 8;
    *(float4*)co = make_float4(acc[0], acc[1], acc[2], acc[3]);
    *(float4*)(co + 4) = make_float4(acc[4], acc[5], acc[6], acc[7]);
}

// ---------------- k3: out = ctx @ out_W^T + out_b + queries  (tf32 wmma, v4) ----------------
// Same as v3 but sw padded: ld 32 -> 36 floats (144B) to kill LDSM bank conflicts.
// grid 512, block 256 (8 warps = 2M x 4N); CTA tile M=32 rows x N=256 oc; K chunks of 32.
#define K3_SC_LD 40
#define K3_SW_LD 36
#define K3_BUF_FLOATS (32 * K3_SC_LD + 256 * K3_SW_LD)  // 1280 + 9216 = 10496
#define K3_SMEM_BYTES (2 * K3_BUF_FLOATS * 4)           // 83968

__global__ __launch_bounds__(256) void k3_out(const float* __restrict__ queries,
                                              const float* __restrict__ out_W,
                                              const float* __restrict__ out_b,
                                              float* __restrict__ out) {
    extern __shared__ __align__(16) float k3sm[];
    const int tid = threadIdx.x;
    const int row0 = blockIdx.x * 32;
    const int warpId = tid >> 5;
    const int lane = tid & 31;
    const int m0 = (warpId & 1) * 16;   // 2 warps along M
    const int n0 = (warpId >> 1) * 64;  // 4 warps along N

    // prefetch of chunk kc into buffer buf
    auto prefetch = [&](int kc, int buf) {
        float* sc = k3sm + buf * K3_BUF_FLOATS;
        float* sw = sc + 32 * K3_SC_LD;
        // ctx: 32 rows x 32 k = 4KB -> 256 x 16B
        {
            int r = tid >> 3, j = tid & 7;
            cp_async16(sc + r * K3_SC_LD + j * 4,
                       g_ctx + (size_t)(row0 + r) * DD + kc * 32 + j * 4);
        }
        // W: 256 oc x 32 k -> 2048 x 16B (dst stride 36 floats = 144B, 16B-aligned)
#pragma unroll
        for (int i = 0; i < 8; i++) {
            int c = tid + i * 256;
            int oc = c >> 3, j = c & 7;
            cp_async16(sw + oc * K3_SW_LD + j * 4, out_W + (size_t)oc * DD + kc * 32 + j * 4);
        }
        cp_commit();
    };

    prefetch(0, 0);

    wmma::fragment<wmma::accumulator, 16, 16, 8, float> cfr[4];
#pragma unroll
    for (int j = 0; j < 4; j++) wmma::fill_fragment(cfr[j], 0.f);

    for (int kc = 0; kc < 8; kc++) {
        if (kc + 1 < 8) {
            prefetch(kc + 1, (kc + 1) & 1);
            cp_wait1();
        } else {
            cp_wait0();
        }
        __syncthreads();

        const float* sc = k3sm + (kc & 1) * K3_BUF_FLOATS;
        const float* sw = sc + 32 * K3_SC_LD;

#pragma unroll
        for (int ks = 0; ks < 4; ks++) { // 32 k / 8
            wmma::fragment<wmma::matrix_a, 16, 16, 8, wmma::precision::tf32, wmma::row_major> afr;
            wmma::fragment<wmma::matrix_b, 16, 16, 8, wmma::precision::tf32, wmma::col_major> bfr[4];
            wmma::load_matrix_sync(afr, sc + m0 * K3_SC_LD + ks * 8, K3_SC_LD);
#pragma unroll
            for (int e = 0; e < afr.num_elements; e++) afr.x[e] = wmma::__float_to_tf32(afr.x[e]);
#pragma unroll
            for (int j = 0; j < 4; j++) {
                // B col-major: element (k, n) at sw[n*K3_SW_LD + k]
                wmma::load_matrix_sync(bfr[j], sw + (n0 + j * 16) * K3_SW_LD + ks * 8, K3_SW_LD);
#pragma unroll
                for (int e = 0; e < bfr[j].num_elements; e++)
                    bfr[j].x[e] = wmma::__float_to_tf32(bfr[j].x[e]);
            }
#pragma unroll
            for (int j = 0; j < 4; j++) wmma::mma_sync(cfr[j], afr, bfr[j], cfr[j]);
        }
        __syncthreads(); // done reading this buffer before it is prefetch-overwritten
    }

    // ---- epilogue: stage, + bias + queries, store ----
    float* stage = k3sm + warpId * 1024; // 16 rows x 64 cols per warp
#pragma unroll
    for (int j = 0; j < 4; j++)
        wmma::store_matrix_sync(stage + j * 16, cfr[j], 64, wmma::mem_row_major);
    __syncwarp();

#pragma unroll
    for (int it = 0; it < 8; it++) {
        int c = it * 32 + lane;  // 256 chunks of 4 cols (16 rows x 16 chunks)
        int r = c >> 4;
        int c4 = (c & 15) * 4;
        int rg = row0 + m0 + r;
        float4 v = *(float4*)(stage + r * 64 + c4);
        float4 bb4 = *(const float4*)&out_b[n0 + c4];
        float4 qv = *(const float4*)&queries[(size_t)rg * DD + n0 + c4];
        v.x += bb4.x + qv.x;
        v.y += bb4.y + qv.y;
        v.z += bb4.z + qv.z;
        v.w += bb4.w + qv.w;
        *(float4*)&out[(size_t)rg * DD + n0 + c4] = v;
    }
}

// ---------------- launch ----------------
extern "C" void kernel_launch(void* const* d_in, const int* in_sizes, int n_in,
                              void* d_out, int out_size) {
    const float* queries = (const float*)d_in[0];
    const float* traj = (const float*)d_in[1];
    const float* bev = (const float*)d_in[2];
    const float* conv_w = (const float*)d_in[3];
    const float* conv_b = (const float*)d_in[4];
    const float* attn_W = (const float*)d_in[5];
    const float* attn_b = (const float*)d_in[6];
    const float* out_W = (const float*)d_in[7];
    const float* out_b = (const float*)d_in[8];
    float* out = (float*)d_out;

    cudaFuncSetAttribute(k1_conv, cudaFuncAttributeMaxDynamicSharedMemorySize, K1_SMEM_BYTES);
    cudaFuncSetAttribute(k3_out, cudaFuncAttributeMaxDynamicSharedMemorySize, K3_SMEM_BYTES);

    k0_wT<<<(9 * CC * DD + 255) / 256, 256>>>(conv_w);
    k1_conv<<<dim3(HH, 2, BB), 256, K1_SMEM_BYTES>>>(bev, conv_b);
    k2_sample<<<(BB * KK) / 8, 256>>>(queries, traj, attn_W, attn_b);
    k3_out<<<(BB * KK) / 32, 256, K3_SMEM_BYTES>>>(queries, out_W, out_b, out);
}